// round 12
// baseline (speedup 1.0000x reference)
#include <cuda_runtime.h>
#include <cuda_bf16.h>
#include <cstdint>

// ---------------------------------------------------------------------------
// GAT layer: h = feat @ W^T ; per-node logits; edge softmax over incoming
// edges; weighted scatter-sum; +feat residual.
// N = 100000, E = 1600000, IN = 128, H = 4, D = 32 (H*D == IN)
//
// Round 11: R10's MLP-4 reverted (L1tex queue overflow). Edge softmax
// weights exp(leaky(es+ed)) are now precomputed in the scatter kernel
// (edge-parallel) and stored per CSR slot, so the aggregate hot loop reads
// them sequentially and only the h-row gather stays on the random-latency
// chain. GEMM joins before scatter (still hidden under hist+scan).
// ---------------------------------------------------------------------------

#define N_MAX 100000
#define E_MAX 1600000
#define SCAN_ELEMS 1024
#define SCAN_BLOCKS ((N_MAX + SCAN_ELEMS - 1) / SCAN_ELEMS)

__device__ __align__(16) float g_h[(size_t)N_MAX * 128];
__device__ __align__(16) float g_es[N_MAX * 4];
__device__ __align__(16) float g_ed[N_MAX * 4];
__device__ __align__(16) int g_deg[((N_MAX + 3) / 4) * 4];
__device__ int g_off[N_MAX];
__device__ int g_pos[N_MAX];
__device__ int g_csr[E_MAX];
__device__ __align__(16) float g_wgt[(size_t)E_MAX * 4];
__device__ int g_partial[SCAN_BLOCKS + 1];
__device__ int g_is64;

// ---------------------------------------------------------------------------
// zero g_deg + detect int64-vs-int32 indices (block 0 warp 0).
// ids < 100000 => odd 32-bit words zero iff int64.
// ---------------------------------------------------------------------------
__global__ void zero_detect_kernel(const unsigned int* __restrict__ w,
                                   int E, int Npad4) {
    int i = blockIdx.x * blockDim.x + threadIdx.x;
    if (i < Npad4) g_deg[i] = 0;
    if (blockIdx.x == 0 && threadIdx.x < 32) {
        int t = threadIdx.x;
        int lim = 1024;
        if (E < 1024) lim = E > 1 ? E - 1 : 1;
        int nz = 0;
        for (int k = t; k < lim; k += 32)
            if (w[2 * k + 1] != 0u) nz++;
        #pragma unroll
        for (int m = 16; m; m >>= 1) nz += __shfl_xor_sync(0xffffffffu, nz, m);
        if (t == 0) g_is64 = (nz < 8) ? 1 : 0;
    }
}

// 2-edge vectorized histogram.
__global__ void hist_kernel(const void* __restrict__ dstp, int E) {
    int is64 = g_is64;
    int stride = gridDim.x * blockDim.x;
    int E2 = E >> 1;
    for (int p = blockIdx.x * blockDim.x + threadIdx.x; p < E2; p += stride) {
        int d0, d1;
        if (is64) {
            ulonglong2 v = ((const ulonglong2*)dstp)[p];
            d0 = (int)v.x; d1 = (int)v.y;
        } else {
            int2 v = ((const int2*)dstp)[p];
            d0 = v.x; d1 = v.y;
        }
        atomicAdd(&g_deg[d0], 1);
        atomicAdd(&g_deg[d1], 1);
    }
    if (blockIdx.x == 0 && threadIdx.x == 0 && (E & 1)) {
        int d = is64 ? (int)((const long long*)dstp)[E - 1]
                     : ((const int*)dstp)[E - 1];
        atomicAdd(&g_deg[d], 1);
    }
}

// ------------------------- two-level scan ----------------------------------
__global__ __launch_bounds__(256) void blocksum_kernel(int nblocks) {
    __shared__ int red[256];
    int b = blockIdx.x, t = threadIdx.x;
    int idx = b * SCAN_ELEMS + t * 4;
    int4 v = make_int4(0, 0, 0, 0);
    if (idx < ((N_MAX + 3) / 4) * 4) v = *(const int4*)(g_deg + idx);
    red[t] = v.x + v.y + v.z + v.w;
    __syncthreads();
    #pragma unroll
    for (int d = 128; d > 0; d >>= 1) {
        if (t < d) red[t] += red[t + d];
        __syncthreads();
    }
    if (t == 0) g_partial[b] = red[0];
}

__global__ __launch_bounds__(128) void scanpartials_kernel(int nblocks) {
    __shared__ int s[128];
    int t = threadIdx.x;
    int v = (t < nblocks) ? g_partial[t] : 0;
    s[t] = v;
    __syncthreads();
    #pragma unroll
    for (int d = 1; d < 128; d <<= 1) {
        int u = (t >= d) ? s[t - d] : 0;
        __syncthreads();
        if (t >= d) s[t] += u;
        __syncthreads();
    }
    if (t < nblocks) g_partial[t] = s[t] - v;
}

__global__ __launch_bounds__(256) void scanwrite_kernel(int N) {
    __shared__ int s[256];
    int b = blockIdx.x, t = threadIdx.x;
    int idx = b * SCAN_ELEMS + t * 4;
    int4 v = make_int4(0, 0, 0, 0);
    if (idx < ((N_MAX + 3) / 4) * 4) v = *(const int4*)(g_deg + idx);
    int tot = v.x + v.y + v.z + v.w;
    s[t] = tot;
    __syncthreads();
    #pragma unroll
    for (int d = 1; d < 256; d <<= 1) {
        int u = (t >= d) ? s[t - d] : 0;
        __syncthreads();
        if (t >= d) s[t] += u;
        __syncthreads();
    }
    int run = g_partial[b] + s[t] - tot;
    int o0 = run, o1 = o0 + v.x, o2 = o1 + v.y, o3 = o2 + v.z;
    if (idx + 0 < N) { g_off[idx + 0] = o0; g_pos[idx + 0] = o0; }
    if (idx + 1 < N) { g_off[idx + 1] = o1; g_pos[idx + 1] = o1; }
    if (idx + 2 < N) { g_off[idx + 2] = o2; g_pos[idx + 2] = o2; }
    if (idx + 3 < N) { g_off[idx + 3] = o3; g_pos[idx + 3] = o3; }
}

// ---------------------------------------------------------------------------
// Scatter + weight precompute: slot = pos[d]++; csr[slot] = s;
// wgt[slot] = exp(leaky(es[s] + ed[d])) for all 4 heads (float4).
// Runs after GEMM (needs g_es/g_ed); edge-parallel, high MLP.
// ---------------------------------------------------------------------------
__global__ void scatter_kernel(const void* __restrict__ srcp,
                               const void* __restrict__ dstp, int E) {
    int is64 = g_is64;
    int stride = gridDim.x * blockDim.x;
    for (int e = blockIdx.x * blockDim.x + threadIdx.x; e < E; e += stride) {
        int d, s;
        if (is64) {
            d = (int)((const long long*)dstp)[e];
            s = (int)((const long long*)srcp)[e];
        } else {
            d = ((const int*)dstp)[e];
            s = ((const int*)srcp)[e];
        }
        int slot = atomicAdd(&g_pos[d], 1);
        float4 es4 = *(const float4*)(g_es + s * 4);
        float4 ed4 = *(const float4*)(g_ed + d * 4);
        float e0 = es4.x + ed4.x; e0 = e0 > 0.f ? e0 : 0.2f * e0;
        float e1 = es4.y + ed4.y; e1 = e1 > 0.f ? e1 : 0.2f * e1;
        float e2 = es4.z + ed4.z; e2 = e2 > 0.f ? e2 : 0.2f * e2;
        float e3 = es4.w + ed4.w; e3 = e3 > 0.f ? e3 : 0.2f * e3;
        float4 w4 = make_float4(__expf(e0), __expf(e1), __expf(e2), __expf(e3));
        g_csr[slot] = s;
        *(float4*)(g_wgt + (size_t)slot * 4) = w4;
    }
}

// ---------------------------------------------------------------------------
// Tensor-core GEMM via portable mma.sync tf32 (m16n8k8, sm_80+ PTX).
// Per CTA: D[128 rows, 128 cols] = feat_tile @ fc_w^T. 256 threads, 8 warps.
// Epilogue: fp32 h store + fused attention dots (quad shfl-reduce).
// ---------------------------------------------------------------------------
#define GPAD 132

__device__ __forceinline__ float cvt_tf32(float x) {
    uint32_t o;
    asm("cvt.rna.tf32.f32 %0, %1;" : "=r"(o) : "f"(x));
    return __uint_as_float(o);
}

__device__ __forceinline__ void mma_tf32(float c[4], uint32_t a0, uint32_t a1,
                                         uint32_t a2, uint32_t a3,
                                         uint32_t b0, uint32_t b1) {
    asm volatile(
        "mma.sync.aligned.m16n8k8.row.col.f32.tf32.tf32.f32 "
        "{%0,%1,%2,%3}, {%4,%5,%6,%7}, {%8,%9}, {%0,%1,%2,%3};"
        : "+f"(c[0]), "+f"(c[1]), "+f"(c[2]), "+f"(c[3])
        : "r"(a0), "r"(a1), "r"(a2), "r"(a3), "r"(b0), "r"(b1));
}

#define GEMM_SMEM (2 * 128 * GPAD * 4 + 1024)

__global__ __launch_bounds__(256) void gemm_mma_kernel(
    const float* __restrict__ feat, const float* __restrict__ fcw,
    const float* __restrict__ asrc, const float* __restrict__ adst, int N) {
    extern __shared__ float sm[];
    float* A_s = sm;                       // [128][GPAD]
    float* B_s = sm + 128 * GPAD;          // [128][GPAD]
    float* s_as = sm + 2 * 128 * GPAD;     // [128]
    float* s_ad = s_as + 128;              // [128]

    int tid = threadIdx.x;
    int w = tid >> 5, lane = tid & 31;
    int qid = lane >> 2;    // groupID 0..7
    int tig = lane & 3;     // threadID in group
    int rowblk = blockIdx.x * 128;

    if (tid < 128) { s_as[tid] = asrc[tid]; s_ad[tid] = adst[tid]; }

    for (int i = tid; i < 128 * 32; i += 256) {
        int r = i >> 5, c4 = (i & 31) * 4;
        float4 wv = *(const float4*)(fcw + (size_t)r * 128 + c4);
        wv.x = cvt_tf32(wv.x); wv.y = cvt_tf32(wv.y);
        wv.z = cvt_tf32(wv.z); wv.w = cvt_tf32(wv.w);
        *(float4*)&B_s[r * GPAD + c4] = wv;
        int gr = rowblk + r;
        float4 fv = make_float4(0.f, 0.f, 0.f, 0.f);
        if (gr < N) fv = *(const float4*)(feat + (size_t)gr * 128 + c4);
        fv.x = cvt_tf32(fv.x); fv.y = cvt_tf32(fv.y);
        fv.z = cvt_tf32(fv.z); fv.w = cvt_tf32(fv.w);
        *(float4*)&A_s[r * GPAD + c4] = fv;
    }
    __syncthreads();

    float acc[16][4];
    #pragma unroll
    for (int j = 0; j < 16; j++)
        acc[j][0] = acc[j][1] = acc[j][2] = acc[j][3] = 0.f;

    int arow = w * 16 + qid;
    #pragma unroll 2
    for (int kb = 0; kb < 16; kb++) {
        int k = kb * 8;
        uint32_t a0 = __float_as_uint(A_s[arow * GPAD + k + tig]);
        uint32_t a1 = __float_as_uint(A_s[(arow + 8) * GPAD + k + tig]);
        uint32_t a2 = __float_as_uint(A_s[arow * GPAD + k + 4 + tig]);
        uint32_t a3 = __float_as_uint(A_s[(arow + 8) * GPAD + k + 4 + tig]);
        #pragma unroll
        for (int j = 0; j < 16; j++) {
            int brow = j * 8 + qid;
            uint32_t b0 = __float_as_uint(B_s[brow * GPAD + k + tig]);
            uint32_t b1 = __float_as_uint(B_s[brow * GPAD + k + 4 + tig]);
            mma_tf32(acc[j], a0, a1, a2, a3, b0, b1);
        }
    }

    // Epilogue: fp32 h store + fused attention dots.
    int row0 = rowblk + w * 16 + qid;
    int row1 = row0 + 8;
    float ps0[4], pd0[4], ps1[4], pd1[4];
    #pragma unroll
    for (int h = 0; h < 4; h++) ps0[h] = pd0[h] = ps1[h] = pd1[h] = 0.f;

    #pragma unroll
    for (int j = 0; j < 16; j++) {
        int col = j * 8 + tig * 2;
        int h = j >> 2;
        float as0 = s_as[col], as1 = s_as[col + 1];
        float ad0 = s_ad[col], ad1 = s_ad[col + 1];
        if (row0 < N)
            *(float2*)(g_h + (size_t)row0 * 128 + col) =
                make_float2(acc[j][0], acc[j][1]);
        if (row1 < N)
            *(float2*)(g_h + (size_t)row1 * 128 + col) =
                make_float2(acc[j][2], acc[j][3]);
        ps0[h] += acc[j][0] * as0 + acc[j][1] * as1;
        pd0[h] += acc[j][0] * ad0 + acc[j][1] * ad1;
        ps1[h] += acc[j][2] * as0 + acc[j][3] * as1;
        pd1[h] += acc[j][2] * ad0 + acc[j][3] * ad1;
    }
    #pragma unroll
    for (int h = 0; h < 4; h++) {
        #pragma unroll
        for (int m = 1; m < 4; m <<= 1) {
            ps0[h] += __shfl_xor_sync(0xffffffffu, ps0[h], m);
            pd0[h] += __shfl_xor_sync(0xffffffffu, pd0[h], m);
            ps1[h] += __shfl_xor_sync(0xffffffffu, ps1[h], m);
            pd1[h] += __shfl_xor_sync(0xffffffffu, pd1[h], m);
        }
    }
    if (tig == 0) {
        if (row0 < N) {
            *(float4*)(g_es + row0 * 4) = make_float4(ps0[0], ps0[1], ps0[2], ps0[3]);
            *(float4*)(g_ed + row0 * 4) = make_float4(pd0[0], pd0[1], pd0[2], pd0[3]);
        }
        if (row1 < N) {
            *(float4*)(g_es + row1 * 4) = make_float4(ps1[0], ps1[1], ps1[2], ps1[3]);
            *(float4*)(g_ed + row1 * 4) = make_float4(pd1[0], pd1[1], pd1[2], pd1[3]);
        }
    }
}

// ---------------------------------------------------------------------------
// Aggregation: one warp per dst node. Weights are precomputed per slot, so
// the loop is: sequential csr/wgt reads (broadcast) + random h-row gather.
// 2-way unrolled => MLP 2 on the only remaining dependent chain.
// ---------------------------------------------------------------------------
__global__ __launch_bounds__(256) void aggregate_kernel(
    const float* __restrict__ feat, float* __restrict__ out, int N) {
    int warp = (blockIdx.x * blockDim.x + threadIdx.x) >> 5;
    int lane = threadIdx.x & 31;
    if (warp >= N) return;
    int start = g_off[warp];
    int cnt = g_deg[warp];
    int head = lane >> 3;

    float4 acc = make_float4(0.f, 0.f, 0.f, 0.f);
    float esum = 0.f;
    const float4* h4 = (const float4*)g_h;
    const float4* w4p = (const float4*)g_wgt;
    int i = 0;
    for (; i + 2 <= cnt; i += 2) {
        int s0 = g_csr[start + i];
        int s1 = g_csr[start + i + 1];
        float4 wa = w4p[start + i];        // broadcast, sequential
        float4 wb = w4p[start + i + 1];
        float4 h0 = h4[(size_t)s0 * 32 + lane];
        float4 h1 = h4[(size_t)s1 * 32 + lane];
        float w0 = (head == 0) ? wa.x : (head == 1) ? wa.y
                 : (head == 2) ? wa.z : wa.w;
        float w1 = (head == 0) ? wb.x : (head == 1) ? wb.y
                 : (head == 2) ? wb.z : wb.w;
        acc.x += w0 * h0.x + w1 * h1.x;
        acc.y += w0 * h0.y + w1 * h1.y;
        acc.z += w0 * h0.z + w1 * h1.z;
        acc.w += w0 * h0.w + w1 * h1.w;
        esum += w0 + w1;
    }
    if (i < cnt) {
        int s0 = g_csr[start + i];
        float4 wa = w4p[start + i];
        float4 h0 = h4[(size_t)s0 * 32 + lane];
        float w0 = (head == 0) ? wa.x : (head == 1) ? wa.y
                 : (head == 2) ? wa.z : wa.w;
        acc.x += w0 * h0.x; acc.y += w0 * h0.y;
        acc.z += w0 * h0.z; acc.w += w0 * h0.w;
        esum += w0;
    }

    float inv = 1.0f / ((esum > 0.f) ? esum : 1.0f);
    float4 fv = ((const float4*)feat)[(size_t)warp * 32 + lane];
    float4 o;
    o.x = fv.x + acc.x * inv;
    o.y = fv.y + acc.y * inv;
    o.z = fv.z + acc.z * inv;
    o.w = fv.w + acc.w * inv;
    ((float4*)out)[(size_t)warp * 32 + lane] = o;
}

// ---------------------------------------------------------------------------
extern "C" void kernel_launch(void* const* d_in, const int* in_sizes, int n_in,
                              void* d_out, int out_size) {
    const float* feat = (const float*)d_in[0];
    const float* fcw  = (const float*)d_in[1];
    const float* asrc = (const float*)d_in[2];
    const float* adst = (const float*)d_in[3];
    const void*  src  = d_in[4];
    const void*  dst  = d_in[5];
    int N = in_sizes[0] / 128;
    int E = in_sizes[4];
    int Npad4 = ((N + 3) / 4) * 4;
    int nblocks = (N + SCAN_ELEMS - 1) / SCAN_ELEMS;

    cudaFuncSetAttribute(gemm_mma_kernel,
                         cudaFuncAttributeMaxDynamicSharedMemorySize, GEMM_SMEM);

    // Fork: GEMM runs concurrently with zero/hist/scan; joins before scatter
    // (scatter consumes g_es/g_ed).
    cudaStream_t s2;
    cudaStreamCreateWithFlags(&s2, cudaStreamNonBlocking);
    cudaEvent_t evFork, evJoin;
    cudaEventCreateWithFlags(&evFork, cudaEventDisableTiming);
    cudaEventCreateWithFlags(&evJoin, cudaEventDisableTiming);

    cudaEventRecord(evFork, 0);
    cudaStreamWaitEvent(s2, evFork, 0);
    gemm_mma_kernel<<<(N + 127) / 128, 256, GEMM_SMEM, s2>>>(feat, fcw, asrc, adst, N);
    cudaEventRecord(evJoin, s2);

    zero_detect_kernel<<<(Npad4 + 255) / 256, 256>>>((const unsigned int*)dst, E, Npad4);
    hist_kernel<<<(E / 2 + 511) / 512, 256>>>(dst, E);
    blocksum_kernel<<<nblocks, 256>>>(nblocks);
    scanpartials_kernel<<<1, 128>>>(nblocks);
    scanwrite_kernel<<<nblocks, 256>>>(N);

    cudaStreamWaitEvent(0, evJoin, 0);   // GEMM results needed by scatter
    scatter_kernel<<<(E + 511) / 512, 256>>>(src, dst, E);
    aggregate_kernel<<<(N + 7) / 8, 256>>>(feat, (float*)d_out, N);

    cudaEventDestroy(evFork);
    cudaEventDestroy(evJoin);
    cudaStreamDestroy(s2);
}

// round 14
// speedup vs baseline: 1.6060x; 1.6060x over previous
#include <cuda_runtime.h>
#include <cuda_bf16.h>
#include <cstdint>

// ---------------------------------------------------------------------------
// GAT layer: h = feat @ W^T ; per-node logits; edge softmax over incoming
// edges; weighted scatter-sum; +feat residual.
// N = 100000, E = 1600000, IN = 128, H = 4, D = 32 (H*D == IN)
//
// Round 13: full revert to R9 (190us) — R11/R12's wgt-precompute thrashed L2
// and serialized GEMM before scatter. On top of R9: aggregate blocks shrunk
// to 64 threads (2 warps) to halve the per-block degree-straggler penalty at
// identical occupancy; detect folded into zero; scatter loads vectorized.
// ---------------------------------------------------------------------------

#define N_MAX 100000
#define E_MAX 1600000
#define SCAN_ELEMS 1024
#define SCAN_BLOCKS ((N_MAX + SCAN_ELEMS - 1) / SCAN_ELEMS)

__device__ __align__(16) float g_h[(size_t)N_MAX * 128];
__device__ __align__(16) float g_es[N_MAX * 4];
__device__ __align__(16) float g_ed[N_MAX * 4];
__device__ __align__(16) int g_deg[((N_MAX + 3) / 4) * 4];
__device__ int g_off[N_MAX];
__device__ int g_pos[N_MAX];
__device__ int g_csr[E_MAX];
__device__ int g_partial[SCAN_BLOCKS + 1];
__device__ int g_is64;

// ---------------------------------------------------------------------------
// zero g_deg + detect int64-vs-int32 indices (block 0 warp 0).
// ids < 100000 => odd 32-bit words zero iff int64.
// ---------------------------------------------------------------------------
__global__ void zero_detect_kernel(const unsigned int* __restrict__ w,
                                   int E, int Npad4) {
    int i = blockIdx.x * blockDim.x + threadIdx.x;
    if (i < Npad4) g_deg[i] = 0;
    if (blockIdx.x == 0 && threadIdx.x < 32) {
        int t = threadIdx.x;
        int lim = 1024;
        if (E < 1024) lim = E > 1 ? E - 1 : 1;
        int nz = 0;
        for (int k = t; k < lim; k += 32)
            if (w[2 * k + 1] != 0u) nz++;
        #pragma unroll
        for (int m = 16; m; m >>= 1) nz += __shfl_xor_sync(0xffffffffu, nz, m);
        if (t == 0) g_is64 = (nz < 8) ? 1 : 0;
    }
}

// 2-edge vectorized histogram.
__global__ void hist_kernel(const void* __restrict__ dstp, int E) {
    int is64 = g_is64;
    int stride = gridDim.x * blockDim.x;
    int E2 = E >> 1;
    for (int p = blockIdx.x * blockDim.x + threadIdx.x; p < E2; p += stride) {
        int d0, d1;
        if (is64) {
            ulonglong2 v = ((const ulonglong2*)dstp)[p];
            d0 = (int)v.x; d1 = (int)v.y;
        } else {
            int2 v = ((const int2*)dstp)[p];
            d0 = v.x; d1 = v.y;
        }
        atomicAdd(&g_deg[d0], 1);
        atomicAdd(&g_deg[d1], 1);
    }
    if (blockIdx.x == 0 && threadIdx.x == 0 && (E & 1)) {
        int d = is64 ? (int)((const long long*)dstp)[E - 1]
                     : ((const int*)dstp)[E - 1];
        atomicAdd(&g_deg[d], 1);
    }
}

// ------------------------- two-level scan ----------------------------------
__global__ __launch_bounds__(256) void blocksum_kernel(int nblocks) {
    __shared__ int red[256];
    int b = blockIdx.x, t = threadIdx.x;
    int idx = b * SCAN_ELEMS + t * 4;
    int4 v = make_int4(0, 0, 0, 0);
    if (idx < ((N_MAX + 3) / 4) * 4) v = *(const int4*)(g_deg + idx);
    red[t] = v.x + v.y + v.z + v.w;
    __syncthreads();
    #pragma unroll
    for (int d = 128; d > 0; d >>= 1) {
        if (t < d) red[t] += red[t + d];
        __syncthreads();
    }
    if (t == 0) g_partial[b] = red[0];
}

__global__ __launch_bounds__(128) void scanpartials_kernel(int nblocks) {
    __shared__ int s[128];
    int t = threadIdx.x;
    int v = (t < nblocks) ? g_partial[t] : 0;
    s[t] = v;
    __syncthreads();
    #pragma unroll
    for (int d = 1; d < 128; d <<= 1) {
        int u = (t >= d) ? s[t - d] : 0;
        __syncthreads();
        if (t >= d) s[t] += u;
        __syncthreads();
    }
    if (t < nblocks) g_partial[t] = s[t] - v;
}

__global__ __launch_bounds__(256) void scanwrite_kernel(int N) {
    __shared__ int s[256];
    int b = blockIdx.x, t = threadIdx.x;
    int idx = b * SCAN_ELEMS + t * 4;
    int4 v = make_int4(0, 0, 0, 0);
    if (idx < ((N_MAX + 3) / 4) * 4) v = *(const int4*)(g_deg + idx);
    int tot = v.x + v.y + v.z + v.w;
    s[t] = tot;
    __syncthreads();
    #pragma unroll
    for (int d = 1; d < 256; d <<= 1) {
        int u = (t >= d) ? s[t - d] : 0;
        __syncthreads();
        if (t >= d) s[t] += u;
        __syncthreads();
    }
    int run = g_partial[b] + s[t] - tot;
    int o0 = run, o1 = o0 + v.x, o2 = o1 + v.y, o3 = o2 + v.z;
    if (idx + 0 < N) { g_off[idx + 0] = o0; g_pos[idx + 0] = o0; }
    if (idx + 1 < N) { g_off[idx + 1] = o1; g_pos[idx + 1] = o1; }
    if (idx + 2 < N) { g_off[idx + 2] = o2; g_pos[idx + 2] = o2; }
    if (idx + 3 < N) { g_off[idx + 3] = o3; g_pos[idx + 3] = o3; }
}

// 2-edge vectorized scatter (csr write only — no extra arrays).
__global__ void scatter_kernel(const void* __restrict__ srcp,
                               const void* __restrict__ dstp, int E) {
    int is64 = g_is64;
    int stride = gridDim.x * blockDim.x;
    int E2 = E >> 1;
    for (int p = blockIdx.x * blockDim.x + threadIdx.x; p < E2; p += stride) {
        int d0, d1, s0, s1;
        if (is64) {
            ulonglong2 dv = ((const ulonglong2*)dstp)[p];
            ulonglong2 sv = ((const ulonglong2*)srcp)[p];
            d0 = (int)dv.x; d1 = (int)dv.y;
            s0 = (int)sv.x; s1 = (int)sv.y;
        } else {
            int2 dv = ((const int2*)dstp)[p];
            int2 sv = ((const int2*)srcp)[p];
            d0 = dv.x; d1 = dv.y;
            s0 = sv.x; s1 = sv.y;
        }
        int slot0 = atomicAdd(&g_pos[d0], 1);
        int slot1 = atomicAdd(&g_pos[d1], 1);
        g_csr[slot0] = s0;
        g_csr[slot1] = s1;
    }
    if (blockIdx.x == 0 && threadIdx.x == 0 && (E & 1)) {
        int d, s;
        if (is64) {
            d = (int)((const long long*)dstp)[E - 1];
            s = (int)((const long long*)srcp)[E - 1];
        } else {
            d = ((const int*)dstp)[E - 1];
            s = ((const int*)srcp)[E - 1];
        }
        int slot = atomicAdd(&g_pos[d], 1);
        g_csr[slot] = s;
    }
}

// ---------------------------------------------------------------------------
// Tensor-core GEMM via portable mma.sync tf32 (m16n8k8, sm_80+ PTX).
// Per CTA: D[128 rows, 128 cols] = feat_tile @ fc_w^T. 256 threads, 8 warps.
// Epilogue: fp32 h store + fused attention dots (quad shfl-reduce).
// ---------------------------------------------------------------------------
#define GPAD 132

__device__ __forceinline__ float cvt_tf32(float x) {
    uint32_t o;
    asm("cvt.rna.tf32.f32 %0, %1;" : "=r"(o) : "f"(x));
    return __uint_as_float(o);
}

__device__ __forceinline__ void mma_tf32(float c[4], uint32_t a0, uint32_t a1,
                                         uint32_t a2, uint32_t a3,
                                         uint32_t b0, uint32_t b1) {
    asm volatile(
        "mma.sync.aligned.m16n8k8.row.col.f32.tf32.tf32.f32 "
        "{%0,%1,%2,%3}, {%4,%5,%6,%7}, {%8,%9}, {%0,%1,%2,%3};"
        : "+f"(c[0]), "+f"(c[1]), "+f"(c[2]), "+f"(c[3])
        : "r"(a0), "r"(a1), "r"(a2), "r"(a3), "r"(b0), "r"(b1));
}

#define GEMM_SMEM (2 * 128 * GPAD * 4 + 1024)

__global__ __launch_bounds__(256) void gemm_mma_kernel(
    const float* __restrict__ feat, const float* __restrict__ fcw,
    const float* __restrict__ asrc, const float* __restrict__ adst, int N) {
    extern __shared__ float sm[];
    float* A_s = sm;                       // [128][GPAD]
    float* B_s = sm + 128 * GPAD;          // [128][GPAD]
    float* s_as = sm + 2 * 128 * GPAD;     // [128]
    float* s_ad = s_as + 128;              // [128]

    int tid = threadIdx.x;
    int w = tid >> 5, lane = tid & 31;
    int qid = lane >> 2;    // groupID 0..7
    int tig = lane & 3;     // threadID in group
    int rowblk = blockIdx.x * 128;

    if (tid < 128) { s_as[tid] = asrc[tid]; s_ad[tid] = adst[tid]; }

    for (int i = tid; i < 128 * 32; i += 256) {
        int r = i >> 5, c4 = (i & 31) * 4;
        float4 wv = *(const float4*)(fcw + (size_t)r * 128 + c4);
        wv.x = cvt_tf32(wv.x); wv.y = cvt_tf32(wv.y);
        wv.z = cvt_tf32(wv.z); wv.w = cvt_tf32(wv.w);
        *(float4*)&B_s[r * GPAD + c4] = wv;
        int gr = rowblk + r;
        float4 fv = make_float4(0.f, 0.f, 0.f, 0.f);
        if (gr < N) fv = *(const float4*)(feat + (size_t)gr * 128 + c4);
        fv.x = cvt_tf32(fv.x); fv.y = cvt_tf32(fv.y);
        fv.z = cvt_tf32(fv.z); fv.w = cvt_tf32(fv.w);
        *(float4*)&A_s[r * GPAD + c4] = fv;
    }
    __syncthreads();

    float acc[16][4];
    #pragma unroll
    for (int j = 0; j < 16; j++)
        acc[j][0] = acc[j][1] = acc[j][2] = acc[j][3] = 0.f;

    int arow = w * 16 + qid;
    #pragma unroll 2
    for (int kb = 0; kb < 16; kb++) {
        int k = kb * 8;
        uint32_t a0 = __float_as_uint(A_s[arow * GPAD + k + tig]);
        uint32_t a1 = __float_as_uint(A_s[(arow + 8) * GPAD + k + tig]);
        uint32_t a2 = __float_as_uint(A_s[arow * GPAD + k + 4 + tig]);
        uint32_t a3 = __float_as_uint(A_s[(arow + 8) * GPAD + k + 4 + tig]);
        #pragma unroll
        for (int j = 0; j < 16; j++) {
            int brow = j * 8 + qid;
            uint32_t b0 = __float_as_uint(B_s[brow * GPAD + k + tig]);
            uint32_t b1 = __float_as_uint(B_s[brow * GPAD + k + 4 + tig]);
            mma_tf32(acc[j], a0, a1, a2, a3, b0, b1);
        }
    }

    // Epilogue: fp32 h store + fused attention dots.
    int row0 = rowblk + w * 16 + qid;
    int row1 = row0 + 8;
    float ps0[4], pd0[4], ps1[4], pd1[4];
    #pragma unroll
    for (int h = 0; h < 4; h++) ps0[h] = pd0[h] = ps1[h] = pd1[h] = 0.f;

    #pragma unroll
    for (int j = 0; j < 16; j++) {
        int col = j * 8 + tig * 2;
        int h = j >> 2;
        float as0 = s_as[col], as1 = s_as[col + 1];
        float ad0 = s_ad[col], ad1 = s_ad[col + 1];
        if (row0 < N)
            *(float2*)(g_h + (size_t)row0 * 128 + col) =
                make_float2(acc[j][0], acc[j][1]);
        if (row1 < N)
            *(float2*)(g_h + (size_t)row1 * 128 + col) =
                make_float2(acc[j][2], acc[j][3]);
        ps0[h] += acc[j][0] * as0 + acc[j][1] * as1;
        pd0[h] += acc[j][0] * ad0 + acc[j][1] * ad1;
        ps1[h] += acc[j][2] * as0 + acc[j][3] * as1;
        pd1[h] += acc[j][2] * ad0 + acc[j][3] * ad1;
    }
    #pragma unroll
    for (int h = 0; h < 4; h++) {
        #pragma unroll
        for (int m = 1; m < 4; m <<= 1) {
            ps0[h] += __shfl_xor_sync(0xffffffffu, ps0[h], m);
            pd0[h] += __shfl_xor_sync(0xffffffffu, pd0[h], m);
            ps1[h] += __shfl_xor_sync(0xffffffffu, ps1[h], m);
            pd1[h] += __shfl_xor_sync(0xffffffffu, pd1[h], m);
        }
    }
    if (tig == 0) {
        if (row0 < N) {
            *(float4*)(g_es + row0 * 4) = make_float4(ps0[0], ps0[1], ps0[2], ps0[3]);
            *(float4*)(g_ed + row0 * 4) = make_float4(pd0[0], pd0[1], pd0[2], pd0[3]);
        }
        if (row1 < N) {
            *(float4*)(g_es + row1 * 4) = make_float4(ps1[0], ps1[1], ps1[2], ps1[3]);
            *(float4*)(g_ed + row1 * 4) = make_float4(pd1[0], pd1[1], pd1[2], pd1[3]);
        }
    }
}

// ---------------------------------------------------------------------------
// Aggregation: one warp per dst node, single fused pass (no max subtraction —
// logits are O(5); exp cannot overflow; softmax is shift-invariant).
// 2-way unrolled inner loop (MLP 2 — the R10 MLP-4 variant overflowed the
// L1tex queue). 64-thread blocks: same 64-warp/SM occupancy as 256, but the
// per-block degree-straggler quantum drops from max-of-8 to max-of-2.
// ---------------------------------------------------------------------------
__global__ __launch_bounds__(64) void aggregate_kernel(
    const float* __restrict__ feat, float* __restrict__ out, int N) {
    int warp = (blockIdx.x * blockDim.x + threadIdx.x) >> 5;
    int lane = threadIdx.x & 31;
    if (warp >= N) return;
    int start = g_off[warp];
    int cnt = g_deg[warp];
    int head = lane >> 3;

    float edh = g_ed[warp * 4 + head];

    float4 acc = make_float4(0.f, 0.f, 0.f, 0.f);
    float esum = 0.f;
    const float4* h4 = (const float4*)g_h;
    int i = 0;
    for (; i + 2 <= cnt; i += 2) {
        int s0 = g_csr[start + i];
        int s1 = g_csr[start + i + 1];
        float e0 = g_es[s0 * 4 + head] + edh;
        float e1 = g_es[s1 * 4 + head] + edh;
        float4 h0 = h4[(size_t)s0 * 32 + lane];
        float4 h1 = h4[(size_t)s1 * 32 + lane];
        e0 = e0 > 0.f ? e0 : 0.2f * e0;
        e1 = e1 > 0.f ? e1 : 0.2f * e1;
        float w0 = __expf(e0);
        float w1 = __expf(e1);
        acc.x += w0 * h0.x + w1 * h1.x;
        acc.y += w0 * h0.y + w1 * h1.y;
        acc.z += w0 * h0.z + w1 * h1.z;
        acc.w += w0 * h0.w + w1 * h1.w;
        esum += w0 + w1;
    }
    if (i < cnt) {
        int s0 = g_csr[start + i];
        float e0 = g_es[s0 * 4 + head] + edh;
        float4 h0 = h4[(size_t)s0 * 32 + lane];
        e0 = e0 > 0.f ? e0 : 0.2f * e0;
        float w0 = __expf(e0);
        acc.x += w0 * h0.x; acc.y += w0 * h0.y;
        acc.z += w0 * h0.z; acc.w += w0 * h0.w;
        esum += w0;
    }

    float inv = 1.0f / ((esum > 0.f) ? esum : 1.0f);
    float4 fv = ((const float4*)feat)[(size_t)warp * 32 + lane];
    float4 o;
    o.x = fv.x + acc.x * inv;
    o.y = fv.y + acc.y * inv;
    o.z = fv.z + acc.z * inv;
    o.w = fv.w + acc.w * inv;
    ((float4*)out)[(size_t)warp * 32 + lane] = o;
}

// ---------------------------------------------------------------------------
extern "C" void kernel_launch(void* const* d_in, const int* in_sizes, int n_in,
                              void* d_out, int out_size) {
    const float* feat = (const float*)d_in[0];
    const float* fcw  = (const float*)d_in[1];
    const float* asrc = (const float*)d_in[2];
    const float* adst = (const float*)d_in[3];
    const void*  src  = d_in[4];
    const void*  dst  = d_in[5];
    int N = in_sizes[0] / 128;
    int E = in_sizes[4];
    int Npad4 = ((N + 3) / 4) * 4;
    int nblocks = (N + SCAN_ELEMS - 1) / SCAN_ELEMS;

    cudaFuncSetAttribute(gemm_mma_kernel,
                         cudaFuncAttributeMaxDynamicSharedMemorySize, GEMM_SMEM);

    // Fork: GEMM on s2 runs concurrently with the CSR build chain.
    cudaStream_t s2;
    cudaStreamCreateWithFlags(&s2, cudaStreamNonBlocking);
    cudaEvent_t evFork, evJoin;
    cudaEventCreateWithFlags(&evFork, cudaEventDisableTiming);
    cudaEventCreateWithFlags(&evJoin, cudaEventDisableTiming);

    cudaEventRecord(evFork, 0);
    cudaStreamWaitEvent(s2, evFork, 0);
    gemm_mma_kernel<<<(N + 127) / 128, 256, GEMM_SMEM, s2>>>(feat, fcw, asrc, adst, N);
    cudaEventRecord(evJoin, s2);

    zero_detect_kernel<<<(Npad4 + 255) / 256, 256>>>((const unsigned int*)dst, E, Npad4);
    hist_kernel<<<(E / 2 + 511) / 512, 256>>>(dst, E);
    blocksum_kernel<<<nblocks, 256>>>(nblocks);
    scanpartials_kernel<<<1, 128>>>(nblocks);
    scanwrite_kernel<<<nblocks, 256>>>(N);
    scatter_kernel<<<(E / 2 + 511) / 512, 256>>>(src, dst, E);

    cudaStreamWaitEvent(0, evJoin, 0);   // join GEMM before aggregate
    aggregate_kernel<<<(N + 1) / 2, 64>>>(feat, (float*)d_out, N);

    cudaEventDestroy(evFork);
    cudaEventDestroy(evJoin);
    cudaStreamDestroy(s2);
}